// round 6
// baseline (speedup 1.0000x reference)
#include <cuda_runtime.h>
#include <cuda_bf16.h>
#include <math.h>
#include <stdint.h>

// Problem constants
#define B_  128
#define T_  256
#define U2_ 1024
#define DA_ 512
#define R_  8
#define SC_ 128
#define OA_ 16
#define NR_ 3

// tcgen05 only exists in the arch-specific (sm_103a) compilation pass.
#if !defined(__CUDA_ARCH__) || defined(__CUDA_ARCH_FEAT_SM103_ALL)
#define TCG_OK 1
#else
#define TCG_OK 0
#endif

// Scratch in __device__ globals (allocation-free rule)
__device__ float g_hbar[(long)B_ * T_ * R_ * DA_];    // [bt, r*DA+a]
__device__ float g_m[(long)B_ * R_ * U2_];            // [b, r*U2+u]
__device__ float g_votes[(long)B_ * R_ * SC_ * OA_];  // [b, r*SC*OA]

// ===========================================================================
// PTX helpers
// ===========================================================================
__device__ __forceinline__ uint32_t smem_u32(const void* p) {
    uint32_t a;
    asm("{ .reg .u64 t; cvta.to.shared.u64 t, %1; cvt.u32.u64 %0, t; }"
        : "=r"(a) : "l"(p));
    return a;
}
__device__ __forceinline__ uint32_t ctarank() {
    uint32_t r;
    asm("mov.u32 %0, %%cluster_ctarank;" : "=r"(r));
    return r;
}

#define MBARRIER_INIT(addr, count) \
    asm volatile("mbarrier.init.shared.b64 [%0], %1;" \
                 :: "r"((uint32_t)(addr)), "r"((uint32_t)(count)) : "memory")

#define MBARRIER_ARRIVE_LOCAL(addr) \
    asm volatile("mbarrier.arrive.shared.b64 _, [%0];" \
                 :: "r"((uint32_t)(addr)) : "memory")

// Arrive on the mbarrier at the same SMEM offset in cluster CTA target_rank.
#define MBARRIER_ARRIVE_CLUSTER(addr, target_rank) \
    asm volatile( \
        "{\n\t" \
        ".reg .b32 remAddr32;\n\t" \
        "mapa.shared::cluster.u32 remAddr32, %0, %1;\n\t" \
        "mbarrier.arrive.shared::cluster.b64 _, [remAddr32];\n\t" \
        "}" \
        :: "r"((uint32_t)(addr)), "r"((uint32_t)(target_rank)) : "memory")

#define MBARRIER_WAIT_PARITY(mbar_smem_addr, phase_parity) do { \
    uint32_t _mbar = (uint32_t)(mbar_smem_addr); \
    uint32_t _parity = (uint32_t)(phase_parity); \
    uint32_t _done; \
    asm volatile( \
        "{\n\t" \
        ".reg .pred p;\n\t" \
        "mbarrier.try_wait.parity.acquire.cta.shared::cta.b64 p, [%1], %2;\n\t" \
        "selp.b32 %0, 1, 0, p;\n\t" \
        "}" \
        : "=r"(_done) : "r"(_mbar), "r"(_parity) : "memory"); \
    if (!_done) { \
        asm volatile( \
            "{\n\t" \
            ".reg .pred P1;\n\t" \
            "WAIT_LOOP_%=:\n\t" \
            "mbarrier.try_wait.parity.acquire.cta.shared::cta.b64 P1, [%0], %1, 0x989680;\n\t" \
            "@P1 bra.uni WAIT_DONE_%=;\n\t" \
            "bra.uni WAIT_LOOP_%=;\n\t" \
            "WAIT_DONE_%=:\n\t" \
            "}" \
            :: "r"(_mbar), "r"(_parity) : "memory"); \
    } \
} while(0)

#define CLUSTER_SYNC() do { \
    asm volatile("barrier.cluster.arrive.aligned;" ::: "memory"); \
    asm volatile("barrier.cluster.wait.aligned;" ::: "memory"); \
} while(0)

#if TCG_OK
#define TCGEN05_ALLOC_CG2(smem_result_addr, nCols) \
    asm volatile("tcgen05.alloc.cta_group::2.sync.aligned.shared::cta.b32 [%0], %1;" \
                 :: "r"((uint32_t)(smem_result_addr)), "r"((uint32_t)(nCols)) : "memory")
#define TCGEN05_DEALLOC_CG2(tmem_addr, nCols) \
    asm volatile("tcgen05.dealloc.cta_group::2.sync.aligned.b32 %0, %1;" \
                 :: "r"(tmem_addr), "r"((uint32_t)(nCols)))
#define TCGEN05_RELINQUISH_CG2() \
    asm volatile("tcgen05.relinquish_alloc_permit.cta_group::2.sync.aligned;")
#define TCGEN05_COMMIT_MC_CG2(mbar, mask) \
    asm volatile("tcgen05.commit.cta_group::2.mbarrier::arrive::one.shared::cluster.multicast::cluster.b64 [%0], %1;" \
                 :: "r"((uint32_t)(mbar)), "h"((uint16_t)(mask)) : "memory")
#define TCGEN05_WAIT_LD() \
    asm volatile("tcgen05.wait::ld.sync.aligned;" ::: "memory")
#define TCGEN05_FENCE_AFTER() \
    asm volatile("tcgen05.fence::after_thread_sync;" ::: "memory")
#define FENCE_PROXY_ASYNC() \
    asm volatile("fence.proxy.async.shared::cta;" ::: "memory")

#define TCGEN05_LD_X32(r, tmem_addr) \
    asm volatile( \
        "tcgen05.ld.sync.aligned.32x32b.x32.b32 " \
        "{%0, %1, %2, %3, %4, %5, %6, %7, " \
        " %8, %9, %10, %11, %12, %13, %14, %15, " \
        " %16, %17, %18, %19, %20, %21, %22, %23, " \
        " %24, %25, %26, %27, %28, %29, %30, %31}, [%32];" \
        : "=r"((r)[0]),  "=r"((r)[1]),  "=r"((r)[2]),  "=r"((r)[3]), \
          "=r"((r)[4]),  "=r"((r)[5]),  "=r"((r)[6]),  "=r"((r)[7]), \
          "=r"((r)[8]),  "=r"((r)[9]),  "=r"((r)[10]), "=r"((r)[11]), \
          "=r"((r)[12]), "=r"((r)[13]), "=r"((r)[14]), "=r"((r)[15]), \
          "=r"((r)[16]), "=r"((r)[17]), "=r"((r)[18]), "=r"((r)[19]), \
          "=r"((r)[20]), "=r"((r)[21]), "=r"((r)[22]), "=r"((r)[23]), \
          "=r"((r)[24]), "=r"((r)[25]), "=r"((r)[26]), "=r"((r)[27]), \
          "=r"((r)[28]), "=r"((r)[29]), "=r"((r)[30]), "=r"((r)[31]) \
        : "r"(tmem_addr))

// tf32 SS MMA, cta_group::2, fp32 accumulate (M across the CTA pair)
__device__ __forceinline__ void mma_tf32_ss_cg2(uint32_t d_tmem, uint64_t a_desc,
                                                uint64_t b_desc, uint32_t idesc,
                                                uint32_t enable) {
    asm volatile(
        "{\n\t"
        ".reg .pred p;\n\t"
        "setp.ne.u32 p, %4, 0;\n\t"
        "tcgen05.mma.cta_group::2.kind::tf32 [%0], %1, %2, %3, p;\n\t"
        "}"
        :: "r"(d_tmem), "l"(a_desc), "l"(b_desc), "r"(idesc), "r"(enable)
        : "memory");
}
#endif // TCG_OK

// SW128 K-major smem descriptor (version=1 Blackwell, LBO=1, SBO=64)
static constexpr uint64_t SMEM_DESC_BASE_SW128 =
    (uint64_t(2)  << 61) | (uint64_t(1) << 46) |
    (uint64_t(64) << 32) | (uint64_t(1) << 16);
#define MAKE_SMEM_DESC(base_addr) \
    (SMEM_DESC_BASE_SW128 | ((uint64_t)((base_addr) >> 4) & 0x3FFF))
#define SWZ128(off) ((off) ^ (((off) >> 3) & 0x70))

__device__ __forceinline__ void cp_async16(uint32_t dst, const void* src) {
    asm volatile("cp.async.cg.shared.global [%0], [%1], 16;"
                 :: "r"(dst), "l"(src) : "memory");
}
__device__ __forceinline__ void cp_async_arrive_noinc(uint32_t mbar) {
    asm volatile("cp.async.mbarrier.arrive.noinc.shared::cta.b64 [%0];"
                 :: "r"(mbar) : "memory");
}

// ===========================================================================
// Pipeline config: stage = A-half 16KB (128 rows) + B-half 32KB (256 rows)
// ===========================================================================
#define NST 3
#define STAGE_BYTES 49152
#define GEMM_DSMEM (1024 + NST * STAGE_BYTES)

// idesc cg2: c=F32(1<<4), a=TF32(2<<7), b=TF32(2<<10), N=256 (32<<17),
// M=256 across pair (16<<24)
static constexpr uint32_t IDESC_TF32_CG2 =
    (1u << 4) | (2u << 7) | (2u << 10) | (32u << 17) | (16u << 24);

// ===========================================================================
// Stage A (cg2): pair tile M=256 x N=512, K=1024.
// hbar = relu(x @ WS1^T);  M=32768, N=4096.
// grid (16, 128): n0 = (bx>>1)*512, m0 = by*256, rank = cluster rank.
// ===========================================================================
__global__ __launch_bounds__(256, 1) __cluster_dims__(2, 1, 1)
void gemm_a(const float* __restrict__ Ag, const float* __restrict__ Bg,
            float* __restrict__ Cg)
{
#if TCG_OK
    constexpr int KT  = 32;
    constexpr int LDC = R_ * DA_;

    extern __shared__ char dyn_smem[];
    __shared__ uint64_t bars[3 * NST + 1];
    __shared__ uint32_t tmem_slot;

    const int tid = threadIdx.x;
    const int n0 = (blockIdx.x >> 1) * 512;
    const int m0 = blockIdx.y * 256;
    const uint32_t rank = ctarank();

    const uint32_t raw = smem_u32(dyn_smem);
    const uint32_t tb = (raw + 1023u) & ~1023u;
    const uint32_t bar_base = smem_u32(&bars[0]);
    const uint32_t full0  = bar_base;
    const uint32_t empty0 = bar_base + NST * 8;
    const uint32_t pairf0 = bar_base + 2 * NST * 8;
    const uint32_t doneb  = bar_base + 3 * NST * 8;

    if (tid == 0) {
#pragma unroll
        for (int s = 0; s < NST; s++) {
            MBARRIER_INIT(full0 + s * 8, 256);
            MBARRIER_INIT(empty0 + s * 8, 1);
            MBARRIER_INIT(pairf0 + s * 8, 2);
        }
        MBARRIER_INIT(doneb, 1);
    }
    if ((tid >> 5) == 0) {
        TCGEN05_ALLOC_CG2(smem_u32(&tmem_slot), 512);
    }
    __syncthreads();
    CLUSTER_SYNC();   // barriers + TMEM visible cluster-wide before use

    uint32_t tmem_base;
    asm volatile("ld.shared.b32 %0, [%1];" : "=r"(tmem_base)
                 : "r"(smem_u32(&tmem_slot)));

    int prod_ph = 1;
    int ph_full = 0, ph_pair = 0;

    for (int it = 0; it < KT + NST - 1; ++it) {
        if (it < KT) {
            const int s = it % NST;
            MBARRIER_WAIT_PARITY(empty0 + s * 8, prod_ph);
            const uint32_t aS = tb + s * STAGE_BYTES;
            const uint32_t bS = aS + 16384;
            const int kbase = it * 32;
#pragma unroll
            for (int i = 0; i < 12; i++) {
                int c = tid + i * 256;       // 0..3071
                if (c < 1024) {              // A-half: 128 m rows
                    int row = c >> 3, ci = c & 7;
                    uint32_t off = SWZ128((uint32_t)(row * 128 + ci * 16));
                    cp_async16(aS + off,
                        Ag + (size_t)(m0 + rank * 128 + row) * U2_ + kbase + ci * 4);
                } else {                     // B-half: 256 n rows (remapped)
                    int c2 = c - 1024;
                    int row = c2 >> 3, ci = c2 & 7;
                    int sub = row >> 7, lrow = row & 127;
                    int n = n0 + sub * 256 + (int)rank * 128 + lrow;
                    uint32_t off = SWZ128((uint32_t)(row * 128 + ci * 16));
                    cp_async16(bS + off,
                        Bg + (size_t)n * U2_ + kbase + ci * 4);
                }
            }
            cp_async_arrive_noinc(full0 + s * 8);
            if (s == NST - 1) prod_ph ^= 1;
        }
        const int ck = it - (NST - 1);
        if (ck >= 0 && tid == 0) {
            const int s = ck % NST;
            MBARRIER_WAIT_PARITY(full0 + s * 8, ph_full);
            if (s == NST - 1) ph_full ^= 1;
            if (rank == 1) {
                MBARRIER_ARRIVE_CLUSTER(pairf0 + s * 8, 0);
            } else {
                MBARRIER_ARRIVE_LOCAL(pairf0 + s * 8);
                MBARRIER_WAIT_PARITY(pairf0 + s * 8, ph_pair);
                if (s == NST - 1) ph_pair ^= 1;
                FENCE_PROXY_ASYNC();
                const uint32_t aS = tb + s * STAGE_BYTES;
                const uint32_t bS = aS + 16384;
                uint64_t ad  = MAKE_SMEM_DESC(aS);
                uint64_t bd0 = MAKE_SMEM_DESC(bS);
                uint64_t bd1 = MAKE_SMEM_DESC(bS + 16384);
#pragma unroll
                for (int ks = 0; ks < 4; ks++) {
                    uint32_t en = (ck > 0 || ks > 0) ? 1u : 0u;
                    mma_tf32_ss_cg2(tmem_base,       ad + 2 * ks, bd0 + 2 * ks,
                                    IDESC_TF32_CG2, en);
                    mma_tf32_ss_cg2(tmem_base + 256, ad + 2 * ks, bd1 + 2 * ks,
                                    IDESC_TF32_CG2, en);
                }
                TCGEN05_COMMIT_MC_CG2(empty0 + s * 8, 0x3);
            }
        }
    }
    if (tid == 0 && rank == 0) TCGEN05_COMMIT_MC_CG2(doneb, 0x3);

    MBARRIER_WAIT_PARITY(doneb, 0);
    TCGEN05_FENCE_AFTER();

    // Epilogue: CTA owns its 128 M-rows x 512 cols.
    const int w = tid >> 5, lane = tid & 31;
    const int grp = w >> 2, sub = w & 3;
    const int mrow = m0 + (int)rank * 128 + sub * 32 + lane;
    float* crow = Cg + (size_t)mrow * LDC + n0 + grp * 256;
    const uint32_t dbase = tmem_base + grp * 256;

#pragma unroll
    for (int ch = 0; ch < 8; ch++) {
        uint32_t rr[32];
        TCGEN05_LD_X32(rr, dbase + ch * 32);
        TCGEN05_WAIT_LD();
#pragma unroll
        for (int j = 0; j < 32; j += 4) {
            float4 v = make_float4(
                fmaxf(__uint_as_float(rr[j + 0]), 0.f),
                fmaxf(__uint_as_float(rr[j + 1]), 0.f),
                fmaxf(__uint_as_float(rr[j + 2]), 0.f),
                fmaxf(__uint_as_float(rr[j + 3]), 0.f));
            *reinterpret_cast<float4*>(crow + ch * 32 + j) = v;
        }
    }

    __syncthreads();
    if ((tid >> 5) == 0) {
        TCGEN05_RELINQUISH_CG2();
        TCGEN05_DEALLOC_CG2(tmem_base, 512);
    }
    CLUSTER_SYNC();
#endif
}

// ===========================================================================
// Fused stage B + C (cg2, b-paired):
//   pair tile M=256 (u) x N=512 = [b0 t-block | b1 t-block], K=512.
//   scoresT[u,t] = WS2_r[u,:] @ hbar_{b,r}[t,:]^T, then register softmax
//   over t + weighted sum against x -> m[b,r,u].
// grid (8, 64, 8): u0=(bx>>1)*256, b0=by*2, r=bz.
// ===========================================================================
__global__ __launch_bounds__(256, 1) __cluster_dims__(2, 1, 1)
void gemm_bc(const float* __restrict__ hbar, const float* __restrict__ WS2,
             const float* __restrict__ x, float* __restrict__ mout)
{
#if TCG_OK
    constexpr int KT  = 16;
    constexpr int LDH = R_ * DA_;

    extern __shared__ char dyn_smem[];
    __shared__ uint64_t bars[3 * NST + 1];
    __shared__ uint32_t tmem_slot;

    const int tid = threadIdx.x;
    const int u0 = (blockIdx.x >> 1) * 256;
    const int b0 = blockIdx.y * 2;
    const int z  = blockIdx.z;
    const uint32_t rank = ctarank();

    const uint32_t raw = smem_u32(dyn_smem);
    const uint32_t tb = (raw + 1023u) & ~1023u;
    const uint32_t bar_base = smem_u32(&bars[0]);
    const uint32_t full0  = bar_base;
    const uint32_t empty0 = bar_base + NST * 8;
    const uint32_t pairf0 = bar_base + 2 * NST * 8;
    const uint32_t doneb  = bar_base + 3 * NST * 8;

    if (tid == 0) {
#pragma unroll
        for (int s = 0; s < NST; s++) {
            MBARRIER_INIT(full0 + s * 8, 256);
            MBARRIER_INIT(empty0 + s * 8, 1);
            MBARRIER_INIT(pairf0 + s * 8, 2);
        }
        MBARRIER_INIT(doneb, 1);
    }
    if ((tid >> 5) == 0) {
        TCGEN05_ALLOC_CG2(smem_u32(&tmem_slot), 512);
    }
    __syncthreads();
    CLUSTER_SYNC();

    uint32_t tmem_base;
    asm volatile("ld.shared.b32 %0, [%1];" : "=r"(tmem_base)
                 : "r"(smem_u32(&tmem_slot)));

    int prod_ph = 1;
    int ph_full = 0, ph_pair = 0;

    for (int it = 0; it < KT + NST - 1; ++it) {
        if (it < KT) {
            const int s = it % NST;
            MBARRIER_WAIT_PARITY(empty0 + s * 8, prod_ph);
            const uint32_t aS = tb + s * STAGE_BYTES;
            const uint32_t bS = aS + 16384;
            const int kbase = it * 32;
#pragma unroll
            for (int i = 0; i < 12; i++) {
                int c = tid + i * 256;
                if (c < 1024) {              // A-half: 128 u rows (WS2)
                    int row = c >> 3, ci = c & 7;
                    int u = u0 + (int)rank * 128 + row;
                    uint32_t off = SWZ128((uint32_t)(row * 128 + ci * 16));
                    cp_async16(aS + off,
                        WS2 + ((size_t)z * U2_ + u) * DA_ + kbase + ci * 4);
                } else {                     // B-half: 256 hbar rows (2 b's)
                    int c2 = c - 1024;
                    int row = c2 >> 3, ci = c2 & 7;
                    int sub = row >> 7, i2 = row & 127;   // sub = which b
                    int bb = b0 + sub;
                    int t = (int)rank * 128 + i2;
                    uint32_t off = SWZ128((uint32_t)(row * 128 + ci * 16));
                    cp_async16(bS + off,
                        hbar + ((size_t)bb * T_ + t) * LDH + z * DA_ + kbase + ci * 4);
                }
            }
            cp_async_arrive_noinc(full0 + s * 8);
            if (s == NST - 1) prod_ph ^= 1;
        }
        const int ck = it - (NST - 1);
        if (ck >= 0 && tid == 0) {
            const int s = ck % NST;
            MBARRIER_WAIT_PARITY(full0 + s * 8, ph_full);
            if (s == NST - 1) ph_full ^= 1;
            if (rank == 1) {
                MBARRIER_ARRIVE_CLUSTER(pairf0 + s * 8, 0);
            } else {
                MBARRIER_ARRIVE_LOCAL(pairf0 + s * 8);
                MBARRIER_WAIT_PARITY(pairf0 + s * 8, ph_pair);
                if (s == NST - 1) ph_pair ^= 1;
                FENCE_PROXY_ASYNC();
                const uint32_t aS = tb + s * STAGE_BYTES;
                const uint32_t bS = aS + 16384;
                uint64_t ad  = MAKE_SMEM_DESC(aS);
                uint64_t bd0 = MAKE_SMEM_DESC(bS);
                uint64_t bd1 = MAKE_SMEM_DESC(bS + 16384);
#pragma unroll
                for (int ks = 0; ks < 4; ks++) {
                    uint32_t en = (ck > 0 || ks > 0) ? 1u : 0u;
                    mma_tf32_ss_cg2(tmem_base,       ad + 2 * ks, bd0 + 2 * ks,
                                    IDESC_TF32_CG2, en);
                    mma_tf32_ss_cg2(tmem_base + 256, ad + 2 * ks, bd1 + 2 * ks,
                                    IDESC_TF32_CG2, en);
                }
                TCGEN05_COMMIT_MC_CG2(empty0 + s * 8, 0x3);
            }
        }
    }
    if (tid == 0 && rank == 0) TCGEN05_COMMIT_MC_CG2(doneb, 0x3);

    MBARRIER_WAIT_PARITY(doneb, 0);
    TCGEN05_FENCE_AFTER();

    // ---- register-resident softmax-weighted-sum epilogue ------------------
    // CTA owns 128 u rows; cols grp*256+t where grp = which b of the pair.
    const int w = tid >> 5, lane = tid & 31;
    const int grp = w >> 2, sub = w & 3;
    const int ug = u0 + (int)rank * 128 + sub * 32 + lane;
    const int bb = b0 + grp;
    const uint32_t dbase = tmem_base + grp * 256;

    const float* xp = x + (size_t)bb * T_ * U2_ + ug;   // stride U2_ over t

    float mx = -3.4e38f, Z = 0.f, W = 0.f;
#pragma unroll
    for (int ch = 0; ch < 8; ch++) {
        uint32_t rr[32];
        TCGEN05_LD_X32(rr, dbase + ch * 32);
        TCGEN05_WAIT_LD();

        float s[32];
        float cmx = -3.4e38f;
#pragma unroll
        for (int j = 0; j < 32; j++) {
            s[j] = __uint_as_float(rr[j]);
            cmx = fmaxf(cmx, s[j]);
        }
        float nm = fmaxf(mx, cmx);
        float resc = __expf(mx - nm);
        Z *= resc;
        W *= resc;
#pragma unroll
        for (int j = 0; j < 32; j++) {
            float e = __expf(s[j] - nm);
            Z += e;
            W = fmaf(e, xp[(size_t)(ch * 32 + j) * U2_], W);
        }
        mx = nm;
    }
    mout[((size_t)bb * R_ + z) * U2_ + ug] = W / Z;

    __syncthreads();
    if ((tid >> 5) == 0) {
        TCGEN05_RELINQUISH_CG2();
        TCGEN05_DEALLOC_CG2(tmem_base, 512);
    }
    CLUSTER_SYNC();
#endif
}

// ===========================================================================
// Stage D: votes_r = m_r @ CW_r. M=128, N=2048 (tiled 64), K=1024, BK=32.
// ===========================================================================
__global__ __launch_bounds__(256)
void sgemm_d(const float* __restrict__ Ag, const float* __restrict__ Bg,
             float* __restrict__ Cg)
{
    const int n0 = blockIdx.x * 64;
    const int z  = blockIdx.z;

    __shared__ float As[32][128 + 4];
    __shared__ float Bs[32][64 + 4];

    const int tid = threadIdx.x;
    const int tx = tid & 15;
    const int ty = tid >> 4;

    float acc[8][4];
#pragma unroll
    for (int i = 0; i < 8; i++)
#pragma unroll
        for (int j = 0; j < 4; j++) acc[i][j] = 0.f;

    for (int k0 = 0; k0 < U2_; k0 += 32) {
#pragma unroll
        for (int i = 0; i < 4; i++) {
            int f = tid + i * 256;
            int row = f >> 3;
            int kk = (f & 7) << 2;
            float4 v = *reinterpret_cast<const float4*>(
                Ag + (size_t)row * (R_ * U2_) + z * U2_ + k0 + kk);
            As[kk + 0][row] = v.x;
            As[kk + 1][row] = v.y;
            As[kk + 2][row] = v.z;
            As[kk + 3][row] = v.w;
        }
#pragma unroll
        for (int i = 0; i < 2; i++) {
            int f = tid + i * 256;
            int kr = f >> 4;
            int nn = (f & 15) << 2;
            float4 v = *reinterpret_cast<const float4*>(
                Bg + ((size_t)z * U2_ + k0 + kr) * (SC_ * OA_) + n0 + nn);
            *reinterpret_cast<float4*>(&Bs[kr][nn]) = v;
        }
        __syncthreads();

#pragma unroll
        for (int k = 0; k < 32; k++) {
            float a[8], bb[4];
            *reinterpret_cast<float4*>(&a[0]) =
                *reinterpret_cast<const float4*>(&As[k][ty * 8]);
            *reinterpret_cast<float4*>(&a[4]) =
                *reinterpret_cast<const float4*>(&As[k][ty * 8 + 4]);
            *reinterpret_cast<float4*>(&bb[0]) =
                *reinterpret_cast<const float4*>(&Bs[k][tx * 4]);
#pragma unroll
            for (int i = 0; i < 8; i++)
#pragma unroll
                for (int j = 0; j < 4; j++)
                    acc[i][j] = fmaf(a[i], bb[j], acc[i][j]);
        }
        __syncthreads();
    }

#pragma unroll
    for (int i = 0; i < 8; i++) {
        size_t row = ty * 8 + i;
        float4 v = make_float4(acc[i][0], acc[i][1], acc[i][2], acc[i][3]);
        *reinterpret_cast<float4*>(
            Cg + row * (R_ * SC_ * OA_) + z * (SC_ * OA_) + n0 + tx * 4) = v;
    }
}

// ===========================================================================
// Stage E: dynamic routing. One block per batch element, 256 threads.
// ===========================================================================
__global__ __launch_bounds__(256)
void routing_kernel(const float* __restrict__ votes, float* __restrict__ out)
{
    const int b = blockIdx.x;
    const int tid = threadIdx.x;
    const float* vb = votes + (long)b * R_ * SC_ * OA_;

    __shared__ float logits[R_][SC_];
    __shared__ float route[R_][SC_];
    __shared__ float act[SC_ * OA_];
    __shared__ float fac[SC_];

    for (int i = tid; i < R_ * SC_; i += 256)
        (&logits[0][0])[i] = 0.f;
    __syncthreads();

    for (int it = 0; it < NR_; it++) {
        int w = tid >> 5, lane = tid & 31;
        if (w < R_) {
            float v0 = logits[w][lane];
            float v1 = logits[w][lane + 32];
            float v2 = logits[w][lane + 64];
            float v3 = logits[w][lane + 96];
            float mx = fmaxf(fmaxf(v0, v1), fmaxf(v2, v3));
#pragma unroll
            for (int off = 16; off; off >>= 1)
                mx = fmaxf(mx, __shfl_xor_sync(0xFFFFFFFFu, mx, off));
            float e0 = expf(v0 - mx), e1 = expf(v1 - mx);
            float e2 = expf(v2 - mx), e3 = expf(v3 - mx);
            float s = e0 + e1 + e2 + e3;
#pragma unroll
            for (int off = 16; off; off >>= 1)
                s += __shfl_xor_sync(0xFFFFFFFFu, s, off);
            float inv = 1.f / s;
            route[w][lane]      = e0 * inv;
            route[w][lane + 32] = e1 * inv;
            route[w][lane + 64] = e2 * inv;
            route[w][lane + 96] = e3 * inv;
        }
        __syncthreads();

        for (int idx = tid; idx < SC_ * OA_; idx += 256) {
            int c = idx >> 4, o = idx & 15;
            float s = 0.f;
#pragma unroll
            for (int r = 0; r < R_; r++)
                s = fmaf(route[r][c], vb[((long)r * SC_ + c) * OA_ + o], s);
            act[idx] = s;
        }
        __syncthreads();

        if (tid < SC_) {
            float n2 = 0.f;
#pragma unroll
            for (int o = 0; o < OA_; o++) {
                float v = act[tid * OA_ + o];
                n2 = fmaf(v, v, n2);
            }
            fac[tid] = sqrtf(n2) / (1.f + n2);
        }
        __syncthreads();
        for (int idx = tid; idx < SC_ * OA_; idx += 256)
            act[idx] *= fac[idx >> 4];
        __syncthreads();

        if (it < NR_ - 1) {
            for (int idx = tid; idx < R_ * SC_; idx += 256) {
                int r = idx >> 7, c = idx & 127;
                float d = 0.f;
#pragma unroll
                for (int o = 0; o < OA_; o++)
                    d = fmaf(vb[((long)r * SC_ + c) * OA_ + o],
                             act[c * OA_ + o], d);
                logits[r][c] += d;
            }
            __syncthreads();
        }
    }

    if (tid < SC_) {
        float n2 = 0.f;
#pragma unroll
        for (int o = 0; o < OA_; o++) {
            float v = act[tid * OA_ + o];
            n2 = fmaf(v, v, n2);
        }
        out[(long)b * SC_ + tid] = sqrtf(n2);
    }
}

// ===========================================================================
extern "C" void kernel_launch(void* const* d_in, const int* in_sizes, int n_in,
                              void* d_out, int out_size)
{
    const float* x   = (const float*)d_in[0];  // [B,T,U2]
    const float* WS1 = (const float*)d_in[1];  // [R,DA,U2]
    const float* WS2 = (const float*)d_in[2];  // [R,U2,DA]
    const float* CW  = (const float*)d_in[3];  // [R,U2,SC*OA]
    float* out = (float*)d_out;                // [B,SC]

    float *hbar, *m, *votes;
    cudaGetSymbolAddress((void**)&hbar,  g_hbar);
    cudaGetSymbolAddress((void**)&m,     g_m);
    cudaGetSymbolAddress((void**)&votes, g_votes);

    cudaFuncSetAttribute(gemm_a,
                         cudaFuncAttributeMaxDynamicSharedMemorySize, GEMM_DSMEM);
    cudaFuncSetAttribute(gemm_bc,
                         cudaFuncAttributeMaxDynamicSharedMemorySize, GEMM_DSMEM);

    // Stage A (cg2): hbar = relu(x @ WS1^T); pair tile 256x512.
    {
        dim3 grid(2 * ((R_ * DA_) / 512), (B_ * T_) / 256, 1);   // (16,128)
        gemm_a<<<grid, 256, GEMM_DSMEM>>>(x, WS1, hbar);
    }

    // Fused B+C (cg2, b-paired): pair tile u256 x [b0,b1]x t256.
    {
        dim3 grid(2 * (U2_ / 256), B_ / 2, R_);                  // (8,64,8)
        gemm_bc<<<grid, 256, GEMM_DSMEM>>>(hbar, WS2, x, m);
    }

    // Stage D: votes_r = m_r @ CW_r (fp32)
    {
        dim3 grid((SC_ * OA_) / 64, 1, R_);
        sgemm_d<<<grid, 256>>>(m, CW, votes);
    }

    // Stage E: dynamic routing + final class logits
    routing_kernel<<<B_, 256>>>(votes, out);
}